// round 5
// baseline (speedup 1.0000x reference)
#include <cuda_runtime.h>

// Problem constants
#define N_    2
#define T_    7
#define C_    96
#define HW_   9216
#define W_    96
#define PTOT  18432      // N_*HW_
#define NHEAD 4
#define HD_   24
#define K3C   288        // 3*C_

// Scratch (static device arrays; no runtime allocation)
__device__ float g_kT[N_ * T_ * HW_ * C_];   // transposed index feats: [(n,t)][pix][c]
__device__ float g_soft[NHEAD * PTOT];       // [head][g]
__device__ int2  g_meta[NHEAD * PTOT];       // [head][g] = {base_offset, valid}

// ---------------------------------------------------------------------------
// K0: transpose idxf (n,t,c,hw) -> g_kT ((n,t),hw,c)
// ---------------------------------------------------------------------------
__global__ void __launch_bounds__(256)
k0_transpose(const float* __restrict__ idxf)
{
    __shared__ float tile[32][33];
    int nt = blockIdx.z;
    int c0 = blockIdx.y * 32;
    int p0 = blockIdx.x * 32;
    int tx = threadIdx.x, ty = threadIdx.y;   // (32,8)

    const float* src = idxf + (nt * C_) * HW_;
#pragma unroll
    for (int i = 0; i < 32; i += 8)
        tile[ty + i][tx] = src[(c0 + ty + i) * HW_ + p0 + tx];
    __syncthreads();
    float* dst = g_kT + (nt * HW_ + p0) * C_;
#pragma unroll
    for (int i = 0; i < 32; i += 8)
        dst[(ty + i) * C_ + c0 + tx] = tile[tx][ty + i];
}

// ---------------------------------------------------------------------------
// K1: correlation + argmax only. Emits soft + winner metadata (no gather).
// ---------------------------------------------------------------------------
__device__ __forceinline__ void red8(float& bs, int& bi)
{
#pragma unroll
    for (int d = 4; d >= 1; d >>= 1) {
        float os = __shfl_xor_sync(0xffffffffu, bs, d, 8);
        int   oi = __shfl_xor_sync(0xffffffffu, bi, d, 8);
        if (os > bs || (os == bs && oi < bi)) { bs = os; bi = oi; }
    }
}

__global__ void __launch_bounds__(256)
k1_corr(const float* __restrict__ curr,
        const float* __restrict__ loc)
{
    __shared__ __align__(16) float sQ[32 * 100];   // [pix][c], pitch 100
    __shared__ float sLoc[2 * T_][32];

    int tx = threadIdx.x;
    int lane8 = tx & 7;
    int pb = tx >> 3;
    int g0 = blockIdx.x * 32;
    int g  = g0 + pb;
    int n = g / HW_;
    int p0blk = g0 - n * HW_;
    int t = lane8;

    {
        const float* qsrc = curr + n * C_ * HW_ + p0blk;
        for (int idx = tx; idx < C_ * 32; idx += 256) {
            int c = idx >> 5, pi = idx & 31;
            sQ[pi * 100 + c] = qsrc[c * HW_ + pi];
        }
    }
    {
        const float* lsrc = loc + (size_t)n * 2 * T_ * HW_ + p0blk;
        for (int idx = tx; idx < 2 * T_ * 32; idx += 256) {
            int pl = idx >> 5, pi = idx & 31;
            sLoc[pl][pi] = lsrc[pl * HW_ + pi];
        }
    }
    __syncthreads();

    bool val = false;
    int lin = 0;
    if (t < T_) {
        float lx = sLoc[2 * t][pb];
        float ly = sLoc[2 * t + 1][pb];
        float gx = __fadd_rn(__fdiv_rn(__fmul_rn(2.0f, lx), 95.0f), -1.0f);
        float gy = __fadd_rn(__fdiv_rn(__fmul_rn(2.0f, ly), 95.0f), -1.0f);
        float ixf = rintf(__fmul_rn(__fmul_rn(__fadd_rn(gx, 1.0f), 0.5f), 95.0f));
        float iyf = rintf(__fmul_rn(__fmul_rn(__fadd_rn(gy, 1.0f), 0.5f), 95.0f));
        val = (ixf >= 0.0f) && (ixf <= 95.0f) && (iyf >= 0.0f) && (iyf <= 95.0f);
        int ix = (int)fminf(fmaxf(ixf, 0.0f), 95.0f);
        int iy = (int)fminf(fmaxf(iyf, 0.0f), 95.0f);
        lin = iy * W_ + ix;
    }

    float sA = 0.f, sB = 0.f, sC = 0.f, sD = 0.f;
    float ksq = 0.f, qsq = 0.f;
    bool doK = (t < T_) && val;
    const float4* kp = (const float4*)(g_kT + ((size_t)(n * T_ + t) * HW_ + lin) * C_);
    const float* qrow = sQ + pb * 100;

#pragma unroll
    for (int c4 = 0; c4 < 24; c4++) {
        float4 k4 = doK ? kp[c4] : make_float4(0.f, 0.f, 0.f, 0.f);
        float4 q4 = *(const float4*)(qrow + c4 * 4);
        qsq = fmaf(q4.x, q4.x, fmaf(q4.y, q4.y, fmaf(q4.z, q4.z, fmaf(q4.w, q4.w, qsq))));
        ksq = fmaf(k4.x, k4.x, fmaf(k4.y, k4.y, fmaf(k4.z, k4.z, fmaf(k4.w, k4.w, ksq))));
        float d = fmaf(q4.x, k4.x, fmaf(q4.y, k4.y, fmaf(q4.z, k4.z, q4.w * k4.w)));
        if      (c4 <  6) sA += d;
        else if (c4 < 12) sB += d;
        else if (c4 < 18) sC += d;
        else              sD += d;
    }

    float rk = 1.0f / fmaxf(sqrtf(ksq), 1e-12f);
    float NEGINF = __int_as_float(0xff800000);
    float b0 = (t < T_) ? sA * rk : NEGINF;
    float b1 = (t < T_) ? sB * rk : NEGINF;
    float b2 = (t < T_) ? sC * rk : NEGINF;
    float b3 = (t < T_) ? sD * rk : NEGINF;
    int i0 = t, i1 = t, i2 = t, i3 = t;
    red8(b0, i0);
    red8(b1, i1);
    red8(b2, i2);
    red8(b3, i3);

    float rq = 1.0f / fmaxf(sqrtf(qsq), 1e-12f);
    if (lane8 == 0) g_soft[0 * PTOT + g] = b0 * rq;
    if (lane8 == 1) g_soft[1 * PTOT + g] = b1 * rq;
    if (lane8 == 2) g_soft[2 * PTOT + g] = b2 * rq;
    if (lane8 == 3) g_soft[3 * PTOT + g] = b3 * rq;

    int vflag = val ? 1 : 0;
    int bw[NHEAD];
    bw[0] = i0; bw[1] = i1; bw[2] = i2; bw[3] = i3;
    // lanes 4..7 write metadata for heads 0..3
    if (lane8 >= 4) {
        int h  = lane8 - 4;
        int lw = __shfl_sync(0xffffffffu, lin,   bw[h], 8);
        int vw = __shfl_sync(0xffffffffu, vflag, bw[h], 8);
        int bofs = ((n * T_ + bw[h]) * C_) * HW_ + lw;
        g_meta[h * PTOT + g] = make_int2(bofs, vw);
    } else {
        // keep shfl participation uniform across the 8-lane group
        __shfl_sync(0xffffffffu, lin,   bw[lane8], 8);
        __shfl_sync(0xffffffffu, vflag, bw[lane8], 8);
    }
}

// ---------------------------------------------------------------------------
// K23 fused: B-tile is GATHERED directly from sp1..3 using winner metadata.
//            U = (Fw @ B + fb) * soft (smem); out = Pw @ U + pb + anchor.
// ---------------------------------------------------------------------------
#define PB 64
#define KB 32
#define BP 68    // Bs/Us column pitch

__global__ void __launch_bounds__(256, 2)
k23_gemm(const float* __restrict__ Fw, const float* __restrict__ fb,
         const float* __restrict__ Pw, const float* __restrict__ pbias,
         const float* __restrict__ anchor, float* __restrict__ out,
         const float* __restrict__ sp1, const float* __restrict__ sp2,
         const float* __restrict__ sp3)
{
    __shared__ float As[KB * 100];
    __shared__ float Bs[KB * BP];
    __shared__ float Us[C_ * BP];
    __shared__ int2  sMeta[NHEAD][PB];

    int g0 = blockIdx.x * PB;
    int n  = g0 / HW_;
    int p0 = g0 - n * HW_;
    int tx = threadIdx.x;
    int m0   = (tx >> 4) * 6;
    int col0 = (tx & 15) * 4;

    // stage winner metadata (coalesced, 256 loads)
    {
        int h = tx >> 6, col = tx & 63;
        sMeta[h][col] = g_meta[h * PTOT + g0 + col];
    }
    __syncthreads();

    float acc[6][4];
#pragma unroll
    for (int j = 0; j < 6; j++)
#pragma unroll
        for (int jj = 0; jj < 4; jj++) acc[j][jj] = 0.0f;

    // register prefetch buffers
    float aR[12];     // Fw chunk: 96*32/256
    float bR[8];      // gathered B chunk: 32*64/256

    // gather one KB-chunk of B into registers
    auto gatherB = [&](int kb) {
        int set = kb / C_;                    // KB=32 divides C_=96
        int cbase = kb - set * C_;
        const float* sp = (set == 0) ? sp1 : ((set == 1) ? sp2 : sp3);
#pragma unroll
        for (int r = 0; r < 8; r++) {
            int i = r * 256 + tx;
            int col = i & 63;
            int kk  = i >> 6;
            int c = cbase + kk;
            int head = c / HD_;
            int2 m = sMeta[head][col];
            bR[r] = m.y ? __ldg(sp + m.x + c * HW_) : 0.0f;
        }
    };

    // prefetch kb = 0
#pragma unroll
    for (int r = 0; r < 12; r++) {
        int i = r * 256 + tx;
        aR[r] = Fw[(i >> 5) * K3C + (i & 31)];
    }
    gatherB(0);

    // ---- phase 1: U = Fw @ gathered-cat ----
    for (int kb = 0; kb < K3C; kb += KB) {
#pragma unroll
        for (int r = 0; r < 12; r++) {
            int i = r * 256 + tx;
            As[(i & 31) * 100 + (i >> 5)] = aR[r];
        }
#pragma unroll
        for (int r = 0; r < 8; r++) {
            int i = r * 256 + tx;
            Bs[(i >> 6) * BP + (i & 63)] = bR[r];
        }
        __syncthreads();

        int kn = kb + KB;
        if (kn < K3C) {
#pragma unroll
            for (int r = 0; r < 12; r++) {
                int i = r * 256 + tx;
                aR[r] = Fw[(i >> 5) * K3C + kn + (i & 31)];
            }
            gatherB(kn);
        }

#pragma unroll
        for (int kk = 0; kk < KB; kk++) {
            float a[6];
#pragma unroll
            for (int j = 0; j < 6; j++) a[j] = As[kk * 100 + m0 + j];
            float4 b = *(const float4*)&Bs[kk * BP + col0];
#pragma unroll
            for (int j = 0; j < 6; j++) {
                acc[j][0] = fmaf(a[j], b.x, acc[j][0]);
                acc[j][1] = fmaf(a[j], b.y, acc[j][1]);
                acc[j][2] = fmaf(a[j], b.z, acc[j][2]);
                acc[j][3] = fmaf(a[j], b.w, acc[j][3]);
            }
        }
        __syncthreads();
    }

    // epilogue 1: +fb, *soft -> Us
    {
        int head = m0 / HD_;
        float4 sf = *(const float4*)&g_soft[head * PTOT + g0 + col0];
#pragma unroll
        for (int j = 0; j < 6; j++) {
            float fbm = fb[m0 + j];
            float4 r;
            r.x = (acc[j][0] + fbm) * sf.x;
            r.y = (acc[j][1] + fbm) * sf.y;
            r.z = (acc[j][2] + fbm) * sf.z;
            r.w = (acc[j][3] + fbm) * sf.w;
            *(float4*)&Us[(m0 + j) * BP + col0] = r;
        }
    }
    __syncthreads();

    // ---- phase 2: out = Pw @ U ----
    float acc2[6][4];
#pragma unroll
    for (int j = 0; j < 6; j++)
#pragma unroll
        for (int jj = 0; jj < 4; jj++) acc2[j][jj] = 0.0f;

    for (int cb = 0; cb < C_; cb += KB) {
        for (int i = tx; i < C_ * KB; i += 256) {
            int d = i >> 5, kk = i & 31;
            As[kk * 100 + d] = Pw[d * C_ + cb + kk];
        }
        __syncthreads();
#pragma unroll
        for (int kk = 0; kk < KB; kk++) {
            float a[6];
#pragma unroll
            for (int j = 0; j < 6; j++) a[j] = As[kk * 100 + m0 + j];
            float4 b = *(const float4*)&Us[(cb + kk) * BP + col0];
#pragma unroll
            for (int j = 0; j < 6; j++) {
                acc2[j][0] = fmaf(a[j], b.x, acc2[j][0]);
                acc2[j][1] = fmaf(a[j], b.y, acc2[j][1]);
                acc2[j][2] = fmaf(a[j], b.z, acc2[j][2]);
                acc2[j][3] = fmaf(a[j], b.w, acc2[j][3]);
            }
        }
        __syncthreads();
    }

    // epilogue 2: + pbias + anchor -> out
#pragma unroll
    for (int j = 0; j < 6; j++) {
        int d = m0 + j;
        float pbd = pbias[d];
        float4 a0 = *(const float4*)(anchor + (size_t)(n * C_ + d) * HW_ + p0 + col0);
        float4 r;
        r.x = acc2[j][0] + pbd + a0.x;
        r.y = acc2[j][1] + pbd + a0.y;
        r.z = acc2[j][2] + pbd + a0.z;
        r.w = acc2[j][3] + pbd + a0.w;
        *(float4*)(out + (size_t)(n * C_ + d) * HW_ + p0 + col0) = r;
    }
}

// ---------------------------------------------------------------------------
extern "C" void kernel_launch(void* const* d_in, const int* in_sizes, int n_in,
                              void* d_out, int out_size)
{
    const float* curr   = (const float*)d_in[0];
    const float* idxf   = (const float*)d_in[1];
    const float* anchor = (const float*)d_in[2];
    const float* s1     = (const float*)d_in[3];
    const float* s2     = (const float*)d_in[4];
    const float* s3     = (const float*)d_in[5];
    const float* loc    = (const float*)d_in[6];
    const float* pw     = (const float*)d_in[7];
    const float* pbv    = (const float*)d_in[8];
    const float* fw     = (const float*)d_in[9];
    const float* fbv    = (const float*)d_in[10];
    float* out = (float*)d_out;

    k0_transpose<<<dim3(HW_ / 32, C_ / 32, N_ * T_), dim3(32, 8)>>>(idxf);
    k1_corr<<<PTOT / 32, 256>>>(curr, loc);
    k23_gemm<<<PTOT / PB, 256>>>(fw, fbv, pw, pbv, anchor, out, s1, s2, s3);
}

// round 6
// speedup vs baseline: 1.1953x; 1.1953x over previous
#include <cuda_runtime.h>

// Problem constants
#define N_    2
#define T_    7
#define C_    96
#define HW_   9216
#define W_    96
#define PTOT  18432      // N_*HW_
#define NHEAD 4
#define HD_   24
#define K3C   288        // 3*C_

// Scratch (static device arrays; no runtime allocation)
__device__ float g_kT[N_ * T_ * HW_ * C_];   // transposed index feats: [(n,t)][pix][c]
__device__ float g_cat[PTOT * K3C];          // [g][k]  k = set*96 + channel
__device__ float g_soft[NHEAD * PTOT];       // [head][g]

// ---------------------------------------------------------------------------
// K0: transpose idxf (n,t,c,hw) -> g_kT ((n,t),hw,c), float4 both sides
// ---------------------------------------------------------------------------
__global__ void __launch_bounds__(256)
k0_transpose(const float* __restrict__ idxf)
{
    __shared__ float tile[32][33];
    int nt = blockIdx.z;
    int c0 = blockIdx.y * 32;
    int p0 = blockIdx.x * 32;
    int tid = threadIdx.x;

    // load: 256 threads, each one float4 along pixels
    {
        int c  = tid >> 3;          // 0..31
        int p4 = (tid & 7) * 4;     // 0..28
        float4 v = *(const float4*)(idxf + (size_t)(nt * C_ + c0 + c) * HW_ + p0 + p4);
        tile[c][p4 + 0] = v.x;
        tile[c][p4 + 1] = v.y;
        tile[c][p4 + 2] = v.z;
        tile[c][p4 + 3] = v.w;
    }
    __syncthreads();
    // store: each thread one float4 along channels
    {
        int p  = tid >> 3;          // 0..31
        int c4 = (tid & 7) * 4;     // 0..28
        float4 o;
        o.x = tile[c4 + 0][p];
        o.y = tile[c4 + 1][p];
        o.z = tile[c4 + 2][p];
        o.w = tile[c4 + 3][p];
        *(float4*)(g_kT + (size_t)(nt * HW_ + p0 + p) * C_ + c0 + c4) = o;
    }
}

// ---------------------------------------------------------------------------
// K1: 8 lanes per pixel; lanes 0..6 own frame t; shfl argmax (first-max);
//     division-free winner gather spread over lanes; cat stored pixel-major.
// ---------------------------------------------------------------------------
__device__ __forceinline__ void red8(float& bs, int& bi)
{
#pragma unroll
    for (int d = 4; d >= 1; d >>= 1) {
        float os = __shfl_xor_sync(0xffffffffu, bs, d, 8);
        int   oi = __shfl_xor_sync(0xffffffffu, bi, d, 8);
        if (os > bs || (os == bs && oi < bi)) { bs = os; bi = oi; }
    }
}

__global__ void __launch_bounds__(256)
k1_corr(const float* __restrict__ curr,
        const float* __restrict__ sp1,
        const float* __restrict__ sp2,
        const float* __restrict__ sp3,
        const float* __restrict__ loc)
{
    __shared__ __align__(16) float sQ[32 * 100];   // [pix][c], pitch 100
    __shared__ float sLoc[2 * T_][32];

    int tx = threadIdx.x;
    int lane8 = tx & 7;
    int pb = tx >> 3;
    int g0 = blockIdx.x * 32;
    int g  = g0 + pb;
    int n = g / HW_;
    int p0blk = g0 - n * HW_;     // block's 32 pixels share n (HW_ % 32 == 0)
    int t = lane8;

    {
        const float* qsrc = curr + n * C_ * HW_ + p0blk;
        for (int idx = tx; idx < C_ * 32; idx += 256) {
            int c = idx >> 5, pi = idx & 31;
            sQ[pi * 100 + c] = qsrc[c * HW_ + pi];
        }
    }
    {
        const float* lsrc = loc + (size_t)n * 2 * T_ * HW_ + p0blk;
        for (int idx = tx; idx < 2 * T_ * 32; idx += 256) {
            int pl = idx >> 5, pi = idx & 31;
            sLoc[pl][pi] = lsrc[pl * HW_ + pi];
        }
    }
    __syncthreads();

    bool val = false;
    int lin = 0;
    if (t < T_) {
        float lx = sLoc[2 * t][pb];
        float ly = sLoc[2 * t + 1][pb];
        float gx = __fadd_rn(__fdiv_rn(__fmul_rn(2.0f, lx), 95.0f), -1.0f);
        float gy = __fadd_rn(__fdiv_rn(__fmul_rn(2.0f, ly), 95.0f), -1.0f);
        float ixf = rintf(__fmul_rn(__fmul_rn(__fadd_rn(gx, 1.0f), 0.5f), 95.0f));
        float iyf = rintf(__fmul_rn(__fmul_rn(__fadd_rn(gy, 1.0f), 0.5f), 95.0f));
        val = (ixf >= 0.0f) && (ixf <= 95.0f) && (iyf >= 0.0f) && (iyf <= 95.0f);
        int ix = (int)fminf(fmaxf(ixf, 0.0f), 95.0f);
        int iy = (int)fminf(fmaxf(iyf, 0.0f), 95.0f);
        lin = iy * W_ + ix;
    }

    float sA = 0.f, sB = 0.f, sC = 0.f, sD = 0.f;
    float ksq = 0.f, qsq = 0.f;
    bool doK = (t < T_) && val;
    const float4* kp = (const float4*)(g_kT + ((size_t)(n * T_ + t) * HW_ + lin) * C_);
    const float* qrow = sQ + pb * 100;

#pragma unroll
    for (int c4 = 0; c4 < 24; c4++) {
        float4 k4 = doK ? kp[c4] : make_float4(0.f, 0.f, 0.f, 0.f);
        float4 q4 = *(const float4*)(qrow + c4 * 4);   // broadcast LDS.128
        qsq = fmaf(q4.x, q4.x, fmaf(q4.y, q4.y, fmaf(q4.z, q4.z, fmaf(q4.w, q4.w, qsq))));
        ksq = fmaf(k4.x, k4.x, fmaf(k4.y, k4.y, fmaf(k4.z, k4.z, fmaf(k4.w, k4.w, ksq))));
        float d = fmaf(q4.x, k4.x, fmaf(q4.y, k4.y, fmaf(q4.z, k4.z, q4.w * k4.w)));
        if      (c4 <  6) sA += d;
        else if (c4 < 12) sB += d;
        else if (c4 < 18) sC += d;
        else              sD += d;
    }

    float rk = 1.0f / fmaxf(sqrtf(ksq), 1e-12f);
    float NEGINF = __int_as_float(0xff800000);
    float b0 = (t < T_) ? sA * rk : NEGINF;
    float b1 = (t < T_) ? sB * rk : NEGINF;
    float b2 = (t < T_) ? sC * rk : NEGINF;
    float b3 = (t < T_) ? sD * rk : NEGINF;
    int i0 = t, i1 = t, i2 = t, i3 = t;
    red8(b0, i0);
    red8(b1, i1);
    red8(b2, i2);
    red8(b3, i3);

    float rq = 1.0f / fmaxf(sqrtf(qsq), 1e-12f);
    if (lane8 == 0) g_soft[0 * PTOT + g] = b0 * rq;
    if (lane8 == 1) g_soft[1 * PTOT + g] = b1 * rq;
    if (lane8 == 2) g_soft[2 * PTOT + g] = b2 * rq;
    if (lane8 == 3) g_soft[3 * PTOT + g] = b3 * rq;

    int vflag = val ? 1 : 0;
    int bw[NHEAD], lw[NHEAD], vw[NHEAD];
    bw[0] = i0; bw[1] = i1; bw[2] = i2; bw[3] = i3;
#pragma unroll
    for (int h = 0; h < NHEAD; h++) {
        lw[h] = __shfl_sync(0xffffffffu, lin,   bw[h], 8);
        vw[h] = __shfl_sync(0xffffffffu, vflag, bw[h], 8);
    }

    float* catg = g_cat + (size_t)g * K3C;
#pragma unroll
    for (int h = 0; h < NHEAD; h++) {
        int bofs = ((n * T_ + bw[h]) * C_ + h * HD_) * HW_ + lw[h];
        bool v = (vw[h] != 0);
#pragma unroll
        for (int set = 0; set < 3; set++) {
            const float* sp = (set == 0) ? sp1 : ((set == 1) ? sp2 : sp3);
#pragma unroll
            for (int j2 = 0; j2 < 3; j2++) {
                int cc = lane8 + j2 * 8;              // 0..23, division-free
                float vv = v ? __ldg(sp + bofs + cc * HW_) : 0.0f;
                catg[set * C_ + h * HD_ + cc] = vv;
            }
        }
    }
}

// ---------------------------------------------------------------------------
// K23 fused: U = (Fw @ cat + fb) * soft (smem); out = Pw @ U + pb + anchor.
//            Both phases register-prefetch their gmem operands.
// ---------------------------------------------------------------------------
#define PB 64
#define KB 32
#define BP 68    // Bs/Us column pitch

__global__ void __launch_bounds__(256, 2)
k23_gemm(const float* __restrict__ Fw, const float* __restrict__ fb,
         const float* __restrict__ Pw, const float* __restrict__ pbias,
         const float* __restrict__ anchor, float* __restrict__ out)
{
    __shared__ float As[KB * 100];
    __shared__ float Bs[KB * BP];
    __shared__ float Us[C_ * BP];

    int g0 = blockIdx.x * PB;
    int n  = g0 / HW_;
    int p0 = g0 - n * HW_;
    int tx = threadIdx.x;
    int m0   = (tx >> 4) * 6;
    int col0 = (tx & 15) * 4;

    float acc[6][4];
#pragma unroll
    for (int j = 0; j < 6; j++)
#pragma unroll
        for (int jj = 0; jj < 4; jj++) acc[j][jj] = 0.0f;

    const float4* cat4 = (const float4*)g_cat;

    float  aR[12];
    float4 bR[2];

#pragma unroll
    for (int r = 0; r < 12; r++) {
        int i = r * 256 + tx;
        aR[r] = Fw[(i >> 5) * K3C + (i & 31)];
    }
#pragma unroll
    for (int r = 0; r < 2; r++) {
        int i = r * 256 + tx;
        bR[r] = cat4[(size_t)(g0 + (i >> 3)) * (K3C / 4) + (i & 7)];
    }

    // ---- phase 1: U = Fw @ cat ----
    for (int kb = 0; kb < K3C; kb += KB) {
#pragma unroll
        for (int r = 0; r < 12; r++) {
            int i = r * 256 + tx;
            As[(i & 31) * 100 + (i >> 5)] = aR[r];
        }
#pragma unroll
        for (int r = 0; r < 2; r++) {
            int i = r * 256 + tx;
            int col = i >> 3, kk = (i & 7) * 4;
            Bs[(kk + 0) * BP + col] = bR[r].x;
            Bs[(kk + 1) * BP + col] = bR[r].y;
            Bs[(kk + 2) * BP + col] = bR[r].z;
            Bs[(kk + 3) * BP + col] = bR[r].w;
        }
        __syncthreads();

        int kn = kb + KB;
        if (kn < K3C) {
#pragma unroll
            for (int r = 0; r < 12; r++) {
                int i = r * 256 + tx;
                aR[r] = Fw[(i >> 5) * K3C + kn + (i & 31)];
            }
#pragma unroll
            for (int r = 0; r < 2; r++) {
                int i = r * 256 + tx;
                bR[r] = cat4[(size_t)(g0 + (i >> 3)) * (K3C / 4) + (kn >> 2) + (i & 7)];
            }
        } else {
            // prefetch Pw chunk 0 for phase 2
#pragma unroll
            for (int r = 0; r < 12; r++) {
                int i = r * 256 + tx;
                aR[r] = Pw[(i >> 5) * C_ + (i & 31)];
            }
        }

#pragma unroll
        for (int kk = 0; kk < KB; kk++) {
            float a[6];
#pragma unroll
            for (int j = 0; j < 6; j++) a[j] = As[kk * 100 + m0 + j];
            float4 b = *(const float4*)&Bs[kk * BP + col0];
#pragma unroll
            for (int j = 0; j < 6; j++) {
                acc[j][0] = fmaf(a[j], b.x, acc[j][0]);
                acc[j][1] = fmaf(a[j], b.y, acc[j][1]);
                acc[j][2] = fmaf(a[j], b.z, acc[j][2]);
                acc[j][3] = fmaf(a[j], b.w, acc[j][3]);
            }
        }
        __syncthreads();
    }

    // epilogue 1: +fb, *soft -> Us
    {
        int head = m0 / HD_;
        float4 sf = *(const float4*)&g_soft[head * PTOT + g0 + col0];
#pragma unroll
        for (int j = 0; j < 6; j++) {
            float fbm = fb[m0 + j];
            float4 r;
            r.x = (acc[j][0] + fbm) * sf.x;
            r.y = (acc[j][1] + fbm) * sf.y;
            r.z = (acc[j][2] + fbm) * sf.z;
            r.w = (acc[j][3] + fbm) * sf.w;
            *(float4*)&Us[(m0 + j) * BP + col0] = r;
        }
    }
    __syncthreads();

    // ---- phase 2: out = Pw @ U ----
    float acc2[6][4];
#pragma unroll
    for (int j = 0; j < 6; j++)
#pragma unroll
        for (int jj = 0; jj < 4; jj++) acc2[j][jj] = 0.0f;

    for (int cb = 0; cb < C_; cb += KB) {
#pragma unroll
        for (int r = 0; r < 12; r++) {
            int i = r * 256 + tx;
            As[(i & 31) * 100 + (i >> 5)] = aR[r];
        }
        __syncthreads();

        int cn = cb + KB;
        if (cn < C_) {
#pragma unroll
            for (int r = 0; r < 12; r++) {
                int i = r * 256 + tx;
                aR[r] = Pw[(i >> 5) * C_ + cn + (i & 31)];
            }
        }

#pragma unroll
        for (int kk = 0; kk < KB; kk++) {
            float a[6];
#pragma unroll
            for (int j = 0; j < 6; j++) a[j] = As[kk * 100 + m0 + j];
            float4 b = *(const float4*)&Us[(cb + kk) * BP + col0];
#pragma unroll
            for (int j = 0; j < 6; j++) {
                acc2[j][0] = fmaf(a[j], b.x, acc2[j][0]);
                acc2[j][1] = fmaf(a[j], b.y, acc2[j][1]);
                acc2[j][2] = fmaf(a[j], b.z, acc2[j][2]);
                acc2[j][3] = fmaf(a[j], b.w, acc2[j][3]);
            }
        }
        __syncthreads();
    }

    // epilogue 2: + pbias + anchor -> out
#pragma unroll
    for (int j = 0; j < 6; j++) {
        int d = m0 + j;
        float pbd = pbias[d];
        float4 a0 = *(const float4*)(anchor + (size_t)(n * C_ + d) * HW_ + p0 + col0);
        float4 r;
        r.x = acc2[j][0] + pbd + a0.x;
        r.y = acc2[j][1] + pbd + a0.y;
        r.z = acc2[j][2] + pbd + a0.z;
        r.w = acc2[j][3] + pbd + a0.w;
        *(float4*)(out + (size_t)(n * C_ + d) * HW_ + p0 + col0) = r;
    }
}

// ---------------------------------------------------------------------------
extern "C" void kernel_launch(void* const* d_in, const int* in_sizes, int n_in,
                              void* d_out, int out_size)
{
    const float* curr   = (const float*)d_in[0];
    const float* idxf   = (const float*)d_in[1];
    const float* anchor = (const float*)d_in[2];
    const float* s1     = (const float*)d_in[3];
    const float* s2     = (const float*)d_in[4];
    const float* s3     = (const float*)d_in[5];
    const float* loc    = (const float*)d_in[6];
    const float* pw     = (const float*)d_in[7];
    const float* pbv    = (const float*)d_in[8];
    const float* fw     = (const float*)d_in[9];
    const float* fbv    = (const float*)d_in[10];
    float* out = (float*)d_out;

    k0_transpose<<<dim3(HW_ / 32, C_ / 32, N_ * T_), 256>>>(idxf);
    k1_corr<<<PTOT / 32, 256>>>(curr, s1, s2, s3, loc);
    k23_gemm<<<PTOT / PB, 256>>>(fw, fbv, pw, pbv, anchor, out);
}

// round 7
// speedup vs baseline: 1.2431x; 1.0400x over previous
#include <cuda_runtime.h>

// Problem constants
#define N_    2
#define T_    7
#define C_    96
#define HW_   9216
#define W_    96
#define PTOT  18432      // N_*HW_
#define NHEAD 4
#define HD_   24
#define K3C   288        // 3*C_

typedef unsigned long long ull;

__device__ __forceinline__ ull pack2(float x, float y) {
    ull r; asm("mov.b64 %0, {%1, %2};" : "=l"(r) : "f"(x), "f"(y)); return r;
}
__device__ __forceinline__ void unpack2(ull v, float& x, float& y) {
    asm("mov.b64 {%0, %1}, %2;" : "=f"(x), "=f"(y) : "l"(v));
}
__device__ __forceinline__ ull ffma2(ull a, ull b, ull c) {
    ull d; asm("fma.rn.f32x2 %0, %1, %2, %3;" : "=l"(d) : "l"(a), "l"(b), "l"(c)); return d;
}

// Scratch (static device arrays; no runtime allocation)
__device__ float g_kT[N_ * T_ * HW_ * C_];   // transposed index feats: [(n,t)][pix][c]
__device__ float g_cat[PTOT * K3C];          // [g][k]
__device__ float g_soft[NHEAD * PTOT];       // [head][g]

// ---------------------------------------------------------------------------
// K0: transpose idxf (n,t,c,hw) -> g_kT ((n,t),hw,c).
//     4 tiles per block, double-buffered, one sync per tile.
// ---------------------------------------------------------------------------
__global__ void __launch_bounds__(256)
k0_transpose(const float* __restrict__ idxf)
{
    __shared__ float tile[2][32][33];
    int nt = blockIdx.z;
    int c0 = blockIdx.y * 32;
    int tid = threadIdx.x;
    int cL = tid >> 3, p4 = (tid & 7) * 4;    // load coords
    int pL = tid >> 3, c4 = (tid & 7) * 4;    // store coords
    int buf = 0;

#pragma unroll
    for (int it = 0; it < 4; it++) {
        int p0 = (blockIdx.x * 4 + it) * 32;
        float4 v = *(const float4*)(idxf + (size_t)(nt * C_ + c0 + cL) * HW_ + p0 + p4);
        tile[buf][cL][p4 + 0] = v.x;
        tile[buf][cL][p4 + 1] = v.y;
        tile[buf][cL][p4 + 2] = v.z;
        tile[buf][cL][p4 + 3] = v.w;
        __syncthreads();
        float4 o;
        o.x = tile[buf][c4 + 0][pL];
        o.y = tile[buf][c4 + 1][pL];
        o.z = tile[buf][c4 + 2][pL];
        o.w = tile[buf][c4 + 3][pL];
        *(float4*)(g_kT + (size_t)(nt * HW_ + p0 + pL) * C_ + c0 + c4) = o;
        buf ^= 1;
    }
}

// ---------------------------------------------------------------------------
// K1: 8 lanes per pixel; lanes 0..6 own frame t; shfl argmax (first-max);
//     division-free winner gather spread over lanes; cat stored pixel-major.
// ---------------------------------------------------------------------------
__device__ __forceinline__ void red8(float& bs, int& bi)
{
#pragma unroll
    for (int d = 4; d >= 1; d >>= 1) {
        float os = __shfl_xor_sync(0xffffffffu, bs, d, 8);
        int   oi = __shfl_xor_sync(0xffffffffu, bi, d, 8);
        if (os > bs || (os == bs && oi < bi)) { bs = os; bi = oi; }
    }
}

__global__ void __launch_bounds__(256)
k1_corr(const float* __restrict__ curr,
        const float* __restrict__ sp1,
        const float* __restrict__ sp2,
        const float* __restrict__ sp3,
        const float* __restrict__ loc)
{
    __shared__ __align__(16) float sQ[32 * 100];   // [pix][c], pitch 100
    __shared__ float sLoc[2 * T_][32];

    int tx = threadIdx.x;
    int lane8 = tx & 7;
    int pb = tx >> 3;
    int g0 = blockIdx.x * 32;
    int g  = g0 + pb;
    int n = g / HW_;
    int p0blk = g0 - n * HW_;
    int t = lane8;

    {
        const float* qsrc = curr + n * C_ * HW_ + p0blk;
        for (int idx = tx; idx < C_ * 32; idx += 256) {
            int c = idx >> 5, pi = idx & 31;
            sQ[pi * 100 + c] = qsrc[c * HW_ + pi];
        }
    }
    {
        const float* lsrc = loc + (size_t)n * 2 * T_ * HW_ + p0blk;
        for (int idx = tx; idx < 2 * T_ * 32; idx += 256) {
            int pl = idx >> 5, pi = idx & 31;
            sLoc[pl][pi] = lsrc[pl * HW_ + pi];
        }
    }
    __syncthreads();

    bool val = false;
    int lin = 0;
    if (t < T_) {
        float lx = sLoc[2 * t][pb];
        float ly = sLoc[2 * t + 1][pb];
        float gx = __fadd_rn(__fdiv_rn(__fmul_rn(2.0f, lx), 95.0f), -1.0f);
        float gy = __fadd_rn(__fdiv_rn(__fmul_rn(2.0f, ly), 95.0f), -1.0f);
        float ixf = rintf(__fmul_rn(__fmul_rn(__fadd_rn(gx, 1.0f), 0.5f), 95.0f));
        float iyf = rintf(__fmul_rn(__fmul_rn(__fadd_rn(gy, 1.0f), 0.5f), 95.0f));
        val = (ixf >= 0.0f) && (ixf <= 95.0f) && (iyf >= 0.0f) && (iyf <= 95.0f);
        int ix = (int)fminf(fmaxf(ixf, 0.0f), 95.0f);
        int iy = (int)fminf(fmaxf(iyf, 0.0f), 95.0f);
        lin = iy * W_ + ix;
    }

    float sA = 0.f, sB = 0.f, sC = 0.f, sD = 0.f;
    float ksq = 0.f, qsq = 0.f;
    bool doK = (t < T_) && val;
    const float4* kp = (const float4*)(g_kT + ((size_t)(n * T_ + t) * HW_ + lin) * C_);
    const float* qrow = sQ + pb * 100;

#pragma unroll
    for (int c4 = 0; c4 < 24; c4++) {
        float4 k4 = doK ? kp[c4] : make_float4(0.f, 0.f, 0.f, 0.f);
        float4 q4 = *(const float4*)(qrow + c4 * 4);
        qsq = fmaf(q4.x, q4.x, fmaf(q4.y, q4.y, fmaf(q4.z, q4.z, fmaf(q4.w, q4.w, qsq))));
        ksq = fmaf(k4.x, k4.x, fmaf(k4.y, k4.y, fmaf(k4.z, k4.z, fmaf(k4.w, k4.w, ksq))));
        float d = fmaf(q4.x, k4.x, fmaf(q4.y, k4.y, fmaf(q4.z, k4.z, q4.w * k4.w)));
        if      (c4 <  6) sA += d;
        else if (c4 < 12) sB += d;
        else if (c4 < 18) sC += d;
        else              sD += d;
    }

    float rk = 1.0f / fmaxf(sqrtf(ksq), 1e-12f);
    float NEGINF = __int_as_float(0xff800000);
    float b0 = (t < T_) ? sA * rk : NEGINF;
    float b1 = (t < T_) ? sB * rk : NEGINF;
    float b2 = (t < T_) ? sC * rk : NEGINF;
    float b3 = (t < T_) ? sD * rk : NEGINF;
    int i0 = t, i1 = t, i2 = t, i3 = t;
    red8(b0, i0);
    red8(b1, i1);
    red8(b2, i2);
    red8(b3, i3);

    float rq = 1.0f / fmaxf(sqrtf(qsq), 1e-12f);
    if (lane8 == 0) g_soft[0 * PTOT + g] = b0 * rq;
    if (lane8 == 1) g_soft[1 * PTOT + g] = b1 * rq;
    if (lane8 == 2) g_soft[2 * PTOT + g] = b2 * rq;
    if (lane8 == 3) g_soft[3 * PTOT + g] = b3 * rq;

    int vflag = val ? 1 : 0;
    int bw[NHEAD], lw[NHEAD], vw[NHEAD];
    bw[0] = i0; bw[1] = i1; bw[2] = i2; bw[3] = i3;
#pragma unroll
    for (int h = 0; h < NHEAD; h++) {
        lw[h] = __shfl_sync(0xffffffffu, lin,   bw[h], 8);
        vw[h] = __shfl_sync(0xffffffffu, vflag, bw[h], 8);
    }

    float* catg = g_cat + (size_t)g * K3C;
#pragma unroll
    for (int h = 0; h < NHEAD; h++) {
        int bofs = ((n * T_ + bw[h]) * C_ + h * HD_) * HW_ + lw[h];
        bool v = (vw[h] != 0);
#pragma unroll
        for (int set = 0; set < 3; set++) {
            const float* sp = (set == 0) ? sp1 : ((set == 1) ? sp2 : sp3);
#pragma unroll
            for (int j2 = 0; j2 < 3; j2++) {
                int cc = lane8 + j2 * 8;
                float vv = v ? __ldg(sp + bofs + cc * HW_) : 0.0f;
                catg[set * C_ + h * HD_ + cc] = vv;
            }
        }
    }
}

// ---------------------------------------------------------------------------
// K23 fused, f32x2-packed FMA (row-pair accumulators).
// ---------------------------------------------------------------------------
#define PB 64
#define KB 32
#define BP 68

__global__ void __launch_bounds__(256, 2)
k23_gemm(const float* __restrict__ Fw, const float* __restrict__ fb,
         const float* __restrict__ Pw, const float* __restrict__ pbias,
         const float* __restrict__ anchor, float* __restrict__ out)
{
    __shared__ float As[KB * 100];
    __shared__ float Bs[KB * BP];
    __shared__ float Us[C_ * BP];

    int g0 = blockIdx.x * PB;
    int n  = g0 / HW_;
    int p0 = g0 - n * HW_;
    int tx = threadIdx.x;
    int m0   = (tx >> 4) * 6;
    int col0 = (tx & 15) * 4;

    ull acc[3][4];   // [row-pair][col], each holds rows (m0+2jp, m0+2jp+1)
#pragma unroll
    for (int jp = 0; jp < 3; jp++)
#pragma unroll
        for (int c = 0; c < 4; c++) acc[jp][c] = 0ull;

    const float4* cat4 = (const float4*)g_cat;

    float  aR[12];
    float4 bR[2];

#pragma unroll
    for (int r = 0; r < 12; r++) {
        int i = r * 256 + tx;
        aR[r] = Fw[(i >> 5) * K3C + (i & 31)];
    }
#pragma unroll
    for (int r = 0; r < 2; r++) {
        int i = r * 256 + tx;
        bR[r] = cat4[(size_t)(g0 + (i >> 3)) * (K3C / 4) + (i & 7)];
    }

    // ---- phase 1: U = Fw @ cat ----
    for (int kb = 0; kb < K3C; kb += KB) {
#pragma unroll
        for (int r = 0; r < 12; r++) {
            int i = r * 256 + tx;
            As[(i & 31) * 100 + (i >> 5)] = aR[r];
        }
#pragma unroll
        for (int r = 0; r < 2; r++) {
            int i = r * 256 + tx;
            int col = i >> 3, kk = (i & 7) * 4;
            Bs[(kk + 0) * BP + col] = bR[r].x;
            Bs[(kk + 1) * BP + col] = bR[r].y;
            Bs[(kk + 2) * BP + col] = bR[r].z;
            Bs[(kk + 3) * BP + col] = bR[r].w;
        }
        __syncthreads();

        int kn = kb + KB;
        if (kn < K3C) {
#pragma unroll
            for (int r = 0; r < 12; r++) {
                int i = r * 256 + tx;
                aR[r] = Fw[(i >> 5) * K3C + kn + (i & 31)];
            }
#pragma unroll
            for (int r = 0; r < 2; r++) {
                int i = r * 256 + tx;
                bR[r] = cat4[(size_t)(g0 + (i >> 3)) * (K3C / 4) + (kn >> 2) + (i & 7)];
            }
        } else {
#pragma unroll
            for (int r = 0; r < 12; r++) {
                int i = r * 256 + tx;
                aR[r] = Pw[(i >> 5) * C_ + (i & 31)];
            }
        }

#pragma unroll
        for (int kk = 0; kk < KB; kk++) {
            // row-pairs of A: contiguous in As -> packed LDS.64
            ull a01 = *(const ull*)&As[kk * 100 + m0];
            ull a23 = *(const ull*)&As[kk * 100 + m0 + 2];
            ull a45 = *(const ull*)&As[kk * 100 + m0 + 4];
            float4 b = *(const float4*)&Bs[kk * BP + col0];
            ull bx = pack2(b.x, b.x), by = pack2(b.y, b.y);
            ull bz = pack2(b.z, b.z), bw = pack2(b.w, b.w);
            acc[0][0] = ffma2(a01, bx, acc[0][0]);
            acc[0][1] = ffma2(a01, by, acc[0][1]);
            acc[0][2] = ffma2(a01, bz, acc[0][2]);
            acc[0][3] = ffma2(a01, bw, acc[0][3]);
            acc[1][0] = ffma2(a23, bx, acc[1][0]);
            acc[1][1] = ffma2(a23, by, acc[1][1]);
            acc[1][2] = ffma2(a23, bz, acc[1][2]);
            acc[1][3] = ffma2(a23, bw, acc[1][3]);
            acc[2][0] = ffma2(a45, bx, acc[2][0]);
            acc[2][1] = ffma2(a45, by, acc[2][1]);
            acc[2][2] = ffma2(a45, bz, acc[2][2]);
            acc[2][3] = ffma2(a45, bw, acc[2][3]);
        }
        __syncthreads();
    }

    // epilogue 1: +fb, *soft -> Us
    {
        int head = m0 / HD_;
        float4 sf = *(const float4*)&g_soft[head * PTOT + g0 + col0];
#pragma unroll
        for (int jp = 0; jp < 3; jp++) {
            int m = m0 + 2 * jp;
            float f0 = fb[m], f1 = fb[m + 1];
            float4 r0, r1;
            unpack2(acc[jp][0], r0.x, r1.x);
            unpack2(acc[jp][1], r0.y, r1.y);
            unpack2(acc[jp][2], r0.z, r1.z);
            unpack2(acc[jp][3], r0.w, r1.w);
            r0.x = (r0.x + f0) * sf.x; r0.y = (r0.y + f0) * sf.y;
            r0.z = (r0.z + f0) * sf.z; r0.w = (r0.w + f0) * sf.w;
            r1.x = (r1.x + f1) * sf.x; r1.y = (r1.y + f1) * sf.y;
            r1.z = (r1.z + f1) * sf.z; r1.w = (r1.w + f1) * sf.w;
            *(float4*)&Us[m * BP + col0] = r0;
            *(float4*)&Us[(m + 1) * BP + col0] = r1;
        }
    }
    __syncthreads();

    // ---- phase 2: out = Pw @ U ----
    ull acc2[3][4];
#pragma unroll
    for (int jp = 0; jp < 3; jp++)
#pragma unroll
        for (int c = 0; c < 4; c++) acc2[jp][c] = 0ull;

    for (int cb = 0; cb < C_; cb += KB) {
#pragma unroll
        for (int r = 0; r < 12; r++) {
            int i = r * 256 + tx;
            As[(i & 31) * 100 + (i >> 5)] = aR[r];
        }
        __syncthreads();

        int cn = cb + KB;
        if (cn < C_) {
#pragma unroll
            for (int r = 0; r < 12; r++) {
                int i = r * 256 + tx;
                aR[r] = Pw[(i >> 5) * C_ + cn + (i & 31)];
            }
        }

#pragma unroll
        for (int kk = 0; kk < KB; kk++) {
            ull a01 = *(const ull*)&As[kk * 100 + m0];
            ull a23 = *(const ull*)&As[kk * 100 + m0 + 2];
            ull a45 = *(const ull*)&As[kk * 100 + m0 + 4];
            float4 b = *(const float4*)&Us[(cb + kk) * BP + col0];
            ull bx = pack2(b.x, b.x), by = pack2(b.y, b.y);
            ull bz = pack2(b.z, b.z), bw = pack2(b.w, b.w);
            acc2[0][0] = ffma2(a01, bx, acc2[0][0]);
            acc2[0][1] = ffma2(a01, by, acc2[0][1]);
            acc2[0][2] = ffma2(a01, bz, acc2[0][2]);
            acc2[0][3] = ffma2(a01, bw, acc2[0][3]);
            acc2[1][0] = ffma2(a23, bx, acc2[1][0]);
            acc2[1][1] = ffma2(a23, by, acc2[1][1]);
            acc2[1][2] = ffma2(a23, bz, acc2[1][2]);
            acc2[1][3] = ffma2(a23, bw, acc2[1][3]);
            acc2[2][0] = ffma2(a45, bx, acc2[2][0]);
            acc2[2][1] = ffma2(a45, by, acc2[2][1]);
            acc2[2][2] = ffma2(a45, bz, acc2[2][2]);
            acc2[2][3] = ffma2(a45, bw, acc2[2][3]);
        }
        __syncthreads();
    }

    // epilogue 2: + pbias + anchor -> out
#pragma unroll
    for (int jp = 0; jp < 3; jp++) {
        int d = m0 + 2 * jp;
        float p0b = pbias[d], p1b = pbias[d + 1];
        float4 a0 = *(const float4*)(anchor + (size_t)(n * C_ + d) * HW_ + p0 + col0);
        float4 a1 = *(const float4*)(anchor + (size_t)(n * C_ + d + 1) * HW_ + p0 + col0);
        float4 r0, r1;
        unpack2(acc2[jp][0], r0.x, r1.x);
        unpack2(acc2[jp][1], r0.y, r1.y);
        unpack2(acc2[jp][2], r0.z, r1.z);
        unpack2(acc2[jp][3], r0.w, r1.w);
        r0.x = r0.x + p0b + a0.x; r0.y = r0.y + p0b + a0.y;
        r0.z = r0.z + p0b + a0.z; r0.w = r0.w + p0b + a0.w;
        r1.x = r1.x + p1b + a1.x; r1.y = r1.y + p1b + a1.y;
        r1.z = r1.z + p1b + a1.z; r1.w = r1.w + p1b + a1.w;
        *(float4*)(out + (size_t)(n * C_ + d) * HW_ + p0 + col0) = r0;
        *(float4*)(out + (size_t)(n * C_ + d + 1) * HW_ + p0 + col0) = r1;
    }
}

// ---------------------------------------------------------------------------
extern "C" void kernel_launch(void* const* d_in, const int* in_sizes, int n_in,
                              void* d_out, int out_size)
{
    const float* curr   = (const float*)d_in[0];
    const float* idxf   = (const float*)d_in[1];
    const float* anchor = (const float*)d_in[2];
    const float* s1     = (const float*)d_in[3];
    const float* s2     = (const float*)d_in[4];
    const float* s3     = (const float*)d_in[5];
    const float* loc    = (const float*)d_in[6];
    const float* pw     = (const float*)d_in[7];
    const float* pbv    = (const float*)d_in[8];
    const float* fw     = (const float*)d_in[9];
    const float* fbv    = (const float*)d_in[10];
    float* out = (float*)d_out;

    k0_transpose<<<dim3(HW_ / 128, C_ / 32, N_ * T_), 256>>>(idxf);
    k1_corr<<<PTOT / 32, 256>>>(curr, s1, s2, s3, loc);
    k23_gemm<<<PTOT / PB, 256>>>(fw, fbv, pw, pbv, anchor, out);
}